// round 16
// baseline (speedup 1.0000x reference)
#include <cuda_runtime.h>
#include <cuda_fp16.h>
#include <math.h>

#define N_   8
#define C_   64
#define T_   256
#define VQ_  90
#define VK_  50
#define L_   4
#define Tq_  252
#define SC_  256
#define NS_  32
#define KSPLIT 8
#define CPB   8
#define KTOT 16128
#define SPQ  22680
#define SPK  12800
#define SPO  23040
#define OUT_TOTAL 11796480
#define BN_COUNT  184320
#define NBLK_BN 720
#define Y_PER_NS 1474560
#define QPAD 96
#define KPAD 56

typedef unsigned long long u64;
typedef unsigned int u32;

// ---- mma / ldmatrix helpers (base PTX) --------------------------------------
__device__ __forceinline__ void mma16(float* c, const u32* a, const u32* b) {
    asm volatile("mma.sync.aligned.m16n8k16.row.col.f32.f16.f16.f32 "
        "{%0,%1,%2,%3},{%4,%5,%6,%7},{%8,%9},{%0,%1,%2,%3};"
        : "+f"(c[0]), "+f"(c[1]), "+f"(c[2]), "+f"(c[3])
        : "r"(a[0]), "r"(a[1]), "r"(a[2]), "r"(a[3]), "r"(b[0]), "r"(b[1]));
}
__device__ __forceinline__ void mma8t(float* c, const u32* a, const u32* b) {
    asm volatile("mma.sync.aligned.m16n8k8.row.col.f32.tf32.tf32.f32 "
        "{%0,%1,%2,%3},{%4,%5,%6,%7},{%8,%9},{%0,%1,%2,%3};"
        : "+f"(c[0]), "+f"(c[1]), "+f"(c[2]), "+f"(c[3])
        : "r"(a[0]), "r"(a[1]), "r"(a[2]), "r"(a[3]), "r"(b[0]), "r"(b[1]));
}
__device__ __forceinline__ u32 tf32u(float x) {
    u32 r; asm("cvt.rna.tf32.f32 %0, %1;" : "=r"(r) : "f"(x)); return r;
}
__device__ __forceinline__ void ldmx4t(u32* r, u32 addr) {
    asm volatile("ldmatrix.sync.aligned.m8n8.x4.trans.shared.b16 {%0,%1,%2,%3},[%4];"
        : "=r"(r[0]), "=r"(r[1]), "=r"(r[2]), "=r"(r[3]) : "r"(addr));
}
__device__ __forceinline__ void ldmx2t(u32* r, u32 addr) {
    asm volatile("ldmatrix.sync.aligned.m8n8.x2.trans.shared.b16 {%0,%1},[%2];"
        : "=r"(r[0]), "=r"(r[1]) : "r"(addr));
}
__device__ __forceinline__ u32 smem_u32(const void* p) {
    u32 a; asm("{ .reg .u64 t; cvta.to.shared.u64 t, %1; cvt.u32.u64 %0, t; }" : "=r"(a) : "l"(p));
    return a;
}
__device__ __forceinline__ void cpa16(u32 dst, const void* src, u32 bytes) {
    asm volatile("cp.async.ca.shared.global [%0], [%1], 16, %2;" :: "r"(dst), "l"(src), "r"(bytes));
}
__device__ __forceinline__ void cpa_commit() { asm volatile("cp.async.commit_group;"); }
__device__ __forceinline__ void cpa_wait2() { asm volatile("cp.async.wait_group 2;" ::: "memory"); }
__device__ __forceinline__ void cpa_wait1() { asm volatile("cp.async.wait_group 1;" ::: "memory"); }
__device__ __forceinline__ void cpa_wait0() { asm volatile("cp.async.wait_group 0;" ::: "memory"); }

// ---------------- scratch ----------------------------------------------------
__device__ __half g_xqh[(long)N_*C_*SPO];
__device__ __half g_xkh[(long)N_*C_*SPK];
__device__ __half g_xvh[(long)N_*C_*SPK];
__device__ __half g_Wqh[16384], g_Wkh[16384], g_Wvh[4096], g_Woh[16384], g_Wdh[4096];
__device__ __half g_Qph[(long)NS_*C_*Tq_*QPAD];   // [ns][c][t][u96], pads stay 0
__device__ __half g_Kph[(long)NS_*C_*T_*KPAD];    // [ns][c][t][v56], pads stay 0
__device__ __half g_Vph[(long)N_*C_*T_*VK_];
__device__ __half g_yh[(long)N_*SC_*T_*VQ_];
__device__ float g_part[(long)KSPLIT*NS_*(L_+1)*VQ_*VK_];
__device__ float g_att[(long)NS_*VQ_*VK_];
__device__ float g_z[(long)OUT_TOTAL];
__device__ float g_d[(long)OUT_TOTAL];
__device__ float g_bnp2[2L*NBLK_BN*64*2];
__device__ float g_bncoef[2*C_*2];

// ---------------- f32 -> fp16 prep -------------------------------------------
__global__ __launch_bounds__(256)
void f2h(const float* __restrict__ s, __half* __restrict__ d, int n2)
{
    int i = blockIdx.x * 256 + threadIdx.x;
    if (i < n2) {
        float2 v = ((const float2*)s)[i];
        ((__half2*)d)[i] = __floats2half2_rn(v.x, v.y);
    }
}

// ---------------- conv1x1: fp16 operands, f32 accum, cp.async 4-stage --------
// A = W fp16 [m][k] (LDS.32 frags), B = X fp16 [k][sp] (ldmatrix.trans)
// out: f32 (+BN partials) or fp16 with (ulen -> upad) row remap
#define CV_WB 3072          // W tile bytes: 64 x 24 halves
#define CV_XB 8448          // X tile bytes: 16 x 264 halves
#define CV_BUF (CV_WB + CV_XB)
#define CONV_SMEM (4 * CV_BUF)
__global__ __launch_bounds__(256, 2)
void conv_h(const __half* __restrict__ W, const float* __restrict__ bias,
            const __half* __restrict__ X, float* Yf, __half* Yh,
            int ulen, int upad, int K, int Nsp, int ldx,
            long xbatch, long ybatch, float* bnsum)
{
    extern __shared__ char smc[];
    const int n  = blockIdx.z;
    const int m0 = blockIdx.y * 64;
    const int n0 = blockIdx.x * 256;
    const __half* Xn = X + (long)n * xbatch;

    const int tid = threadIdx.x, w = tid >> 5, lane = tid & 31;
    const int g = lane >> 2, tg = lane & 3;
    const int grp = lane >> 3, r = lane & 7;
    const int mw = (w & 1) * 32, nw = (w >> 1) * 64;
    const int KT = K >> 4;
    const u32 sm0 = smem_u32(smc);

    auto issue = [&](int kt) {
        const u32 base = sm0 + (u32)(kt & 3) * CV_BUF;
        const int k0 = kt * 16;
        if (tid < 128) {
            int row = tid >> 1, ch = tid & 1;
            cpa16(base + (u32)(row * 24 + ch * 8) * 2,
                  W + (long)(m0 + row) * K + k0 + ch * 8, 16);
        }
        #pragma unroll
        for (int p = 0; p < 2; p++) {
            int id = tid + p * 256;
            int kk = id >> 5, ch = id & 31;
            int col = n0 + ch * 8;
            int hb = Nsp - col;
            u32 sz = hb <= 0 ? 0u : (hb >= 8 ? 16u : (u32)hb * 2);
            const __half* src = Xn + (long)(k0 + kk) * ldx + (sz ? col : 0);
            cpa16(base + (u32)(CV_WB + (kk * 264 + ch * 8) * 2), src, sz);
        }
        cpa_commit();
    };

    float acc[2][8][4];
    #pragma unroll
    for (int i = 0; i < 2; i++)
        #pragma unroll
        for (int j = 0; j < 8; j++)
            #pragma unroll
            for (int e = 0; e < 4; e++) acc[i][j][e] = 0.f;

    issue(0);
    if (KT > 1) issue(1);
    if (KT > 2) issue(2);

    for (int kt = 0; kt < KT; kt++) {
        int rem = KT - kt - 1; rem = rem > 2 ? 2 : rem;
        if (rem == 2) cpa_wait2(); else if (rem == 1) cpa_wait1(); else cpa_wait0();
        __syncthreads();
        if (kt + 3 < KT) issue(kt + 3);
        const char* Wb = smc + (kt & 3) * CV_BUF;
        const u32 Xb = sm0 + (u32)(kt & 3) * CV_BUF + CV_WB;

        u32 a[2][4];
        #pragma unroll
        for (int mi = 0; mi < 2; mi++) {
            int mA = mw + mi * 16;
            a[mi][0] = *(const u32*)(Wb + ((mA + g) * 24 + 2 * tg) * 2);
            a[mi][1] = *(const u32*)(Wb + ((mA + g + 8) * 24 + 2 * tg) * 2);
            a[mi][2] = *(const u32*)(Wb + ((mA + g) * 24 + 2 * tg + 8) * 2);
            a[mi][3] = *(const u32*)(Wb + ((mA + g + 8) * 24 + 2 * tg + 8) * 2);
        }
        u32 bb[8][2];
        #pragma unroll
        for (int j = 0; j < 4; j++) {
            u32 r4[4];
            u32 addr = Xb + (u32)((((grp & 1) * 8 + r) * 264 + nw + j * 16 + (grp >> 1) * 8) * 2);
            ldmx4t(r4, addr);
            bb[2*j][0] = r4[0]; bb[2*j][1] = r4[1];
            bb[2*j+1][0] = r4[2]; bb[2*j+1][1] = r4[3];
        }
        #pragma unroll
        for (int mi = 0; mi < 2; mi++)
            #pragma unroll
            for (int ji = 0; ji < 8; ji++) mma16(acc[mi][ji], a[mi], bb[ji]);
        __syncthreads();
    }

    if (Yh) {   // fp16 output with row remap (ulen -> upad)
        __half* Yn = Yh + (long)n * ybatch;
        const int TR = Nsp / ulen;
        #pragma unroll
        for (int mi = 0; mi < 2; mi++) {
            int mrow = m0 + mw + mi * 16 + g;
            float bv0 = bias[mrow], bv1 = bias[mrow + 8];
            #pragma unroll
            for (int ji = 0; ji < 8; ji++) {
                int sp = n0 + nw + ji * 8 + 2 * tg;
                if (sp < Nsp) {
                    int t = sp / ulen, u = sp - t * ulen;
                    __half2 h0 = __floats2half2_rn(acc[mi][ji][0] + bv0, acc[mi][ji][1] + bv0);
                    __half2 h1 = __floats2half2_rn(acc[mi][ji][2] + bv1, acc[mi][ji][3] + bv1);
                    long o0 = ((long)mrow * TR + t) * upad + u;
                    long o1 = ((long)(mrow + 8) * TR + t) * upad + u;
                    if (u + 1 < ulen) {
                        *(__half2*)&Yn[o0] = h0;
                        *(__half2*)&Yn[o1] = h1;
                    } else {
                        Yn[o0] = __low2half(h0);
                        Yn[((long)mrow * TR + t + 1) * upad] = __high2half(h0);
                        Yn[o1] = __low2half(h1);
                        Yn[((long)(mrow + 8) * TR + t + 1) * upad] = __high2half(h1);
                    }
                }
            }
        }
    } else {    // f32 output + optional BN partials
        float* Yn = Yf + (long)n * ybatch;
        float s1l[4] = {0.f,0.f,0.f,0.f}, s2l[4] = {0.f,0.f,0.f,0.f};
        #pragma unroll
        for (int mi = 0; mi < 2; mi++) {
            int mrow = m0 + mw + mi * 16 + g;
            float bv0 = bias[mrow], bv1 = bias[mrow + 8];
            #pragma unroll
            for (int ji = 0; ji < 8; ji++) {
                int col = n0 + nw + ji * 8 + 2 * tg;
                if (col < Nsp) {
                    float2 o0; o0.x = acc[mi][ji][0] + bv0; o0.y = acc[mi][ji][1] + bv0;
                    float2 o1; o1.x = acc[mi][ji][2] + bv1; o1.y = acc[mi][ji][3] + bv1;
                    *(float2*)&Yn[(long)mrow * Nsp + col] = o0;
                    *(float2*)&Yn[(long)(mrow + 8) * Nsp + col] = o1;
                    if (bnsum) {
                        s1l[mi*2+0] += o0.x + o0.y;  s2l[mi*2+0] += o0.x*o0.x + o0.y*o0.y;
                        s1l[mi*2+1] += o1.x + o1.y;  s2l[mi*2+1] += o1.x*o1.x + o1.y*o1.y;
                    }
                }
            }
        }
        if (bnsum) {
            #pragma unroll
            for (int rr = 0; rr < 4; rr++) {
                s1l[rr] += __shfl_xor_sync(0xffffffffu, s1l[rr], 1);
                s1l[rr] += __shfl_xor_sync(0xffffffffu, s1l[rr], 2);
                s2l[rr] += __shfl_xor_sync(0xffffffffu, s2l[rr], 1);
                s2l[rr] += __shfl_xor_sync(0xffffffffu, s2l[rr], 2);
            }
            float* bs = (float*)smc;
            if (tg == 0) {
                #pragma unroll
                for (int rr = 0; rr < 4; rr++) {
                    int row = mw + (rr >> 1) * 16 + g + (rr & 1) * 8;
                    bs[(row * 4 + (w >> 1)) * 2 + 0] = s1l[rr];
                    bs[(row * 4 + (w >> 1)) * 2 + 1] = s2l[rr];
                }
            }
            __syncthreads();
            if (tid < 64) {
                float a1 = 0.f, a2 = 0.f;
                #pragma unroll
                for (int j = 0; j < 4; j++) {
                    a1 += bs[(tid * 4 + j) * 2 + 0];
                    a2 += bs[(tid * 4 + j) * 2 + 1];
                }
                int blk = blockIdx.x * gridDim.z + blockIdx.z;
                ((float2*)bnsum)[(long)blk * 64 + tid] = make_float2(a1, a2);
            }
        }
    }
}

// ---------------- score: fp16 m16n8k16, all 5 lags, cp.async 4-stage ---------
// part_l[u][v] = sum_{c,t} Qp[ns][c][t][u] * Kp[ns][c][t+l][v]
// A = Q (ldmatrix.trans from [t][u96]), B = K (ldmatrix.trans, lag = row offset)
#define SQ_B (32*104*2)     // Q tile: 32 t x 104 halves
#define SK_B (36*56*2)      // K tile: 36 t x 56 halves
#define SC_BUF (SQ_B + SK_B)
#define SC_SMEM (4 * SC_BUF)
__global__ __launch_bounds__(320)
void score_h(const __half* __restrict__ Qh, const __half* __restrict__ Kh,
             float* __restrict__ part)
{
    extern __shared__ char smc[];
    const int ns = blockIdx.x, ksb = blockIdx.y;
    const int tid = threadIdx.x, w = tid >> 5, lane = tid & 31;
    const int g = lane >> 2, tg = lane & 3;
    const int grp = lane >> 3, r = lane & 7;
    const int l = w >> 1, uh = w & 1;
    const __half* Qns = Qh + (long)ns * C_ * Tq_ * QPAD;
    const __half* Kns = Kh + (long)ns * C_ * T_ * KPAD;
    const u32 sm0 = smem_u32(smc);

    // 2 staging jobs per thread: ids 0..383 = Q (row/12, ch%12), 384..635 = K
    int jrow[2], jch[2], jq[2];
    u32 jdst[2];
    #pragma unroll
    for (int p = 0; p < 2; p++) {
        int id = tid + p * 320;
        if (id < 384) {
            jq[p] = 1; jrow[p] = id / 12; jch[p] = id % 12;
            jdst[p] = (u32)((jrow[p] * 104 + jch[p] * 8) * 2);
        } else if (id < 636) {
            int id2 = id - 384;
            jq[p] = 0; jrow[p] = id2 / 7; jch[p] = id2 % 7;
            jdst[p] = (u32)(SQ_B + (jrow[p] * 56 + jch[p] * 8) * 2);
        } else jq[p] = -1;
    }

    auto issue = [&](int it) {
        const int c = ksb * CPB + (it >> 3), tt = it & 7;
        const int t0 = tt * 32;
        const u32 base = sm0 + (u32)(it & 3) * SC_BUF;
        const __half* Qc = Qns + (long)c * Tq_ * QPAD;
        const __half* Kc = Kns + (long)c * T_ * KPAD;
        #pragma unroll
        for (int p = 0; p < 2; p++) {
            if (jq[p] == 1) {
                int t = t0 + jrow[p];
                u32 sz = (t < Tq_) ? (jch[p] == 11 ? 4u : 16u) : 0u;
                cpa16(base + jdst[p], sz ? (Qc + (long)t * QPAD + jch[p] * 8) : Qc, sz);
            } else if (jq[p] == 0) {
                int t = t0 + jrow[p];
                u32 sz = (t < T_) ? (jch[p] == 6 ? 4u : 16u) : 0u;
                cpa16(base + jdst[p], sz ? (Kc + (long)t * KPAD + jch[p] * 8) : Kc, sz);
            }
        }
        cpa_commit();
    };

    float acc[3][7][4];
    #pragma unroll
    for (int i = 0; i < 3; i++)
        #pragma unroll
        for (int j = 0; j < 7; j++)
            #pragma unroll
            for (int e = 0; e < 4; e++) acc[i][j][e] = 0.f;

    const int NT = CPB * 8;   // 64 tiles of 32 t
    issue(0); issue(1); issue(2);

    for (int it = 0; it < NT; it++) {
        int rem = NT - it - 1; rem = rem > 2 ? 2 : rem;
        if (rem == 2) cpa_wait2(); else if (rem == 1) cpa_wait1(); else cpa_wait0();
        __syncthreads();
        if (it + 3 < NT) issue(it + 3);
        const u32 Qb = sm0 + (u32)(it & 3) * SC_BUF;
        const u32 Kb = Qb + SQ_B;
        #pragma unroll
        for (int k16 = 0; k16 < 2; k16++) {
            const int k0 = k16 * 16;
            u32 a[3][4], bb[7][2];
            #pragma unroll
            for (int i = 0; i < 3; i++) {
                u32 addr = Qb + (u32)((((k0 + (grp >> 1) * 8 + r) * 104)
                           + uh * 48 + i * 16 + (grp & 1) * 8) * 2);
                ldmx4t(a[i], addr);
            }
            #pragma unroll
            for (int j2 = 0; j2 < 3; j2++) {
                u32 r4[4];
                u32 addr = Kb + (u32)((((k0 + l + (grp & 1) * 8 + r) * 56)
                           + j2 * 16 + (grp >> 1) * 8) * 2);
                ldmx4t(r4, addr);
                bb[2*j2][0] = r4[0]; bb[2*j2][1] = r4[1];
                bb[2*j2+1][0] = r4[2]; bb[2*j2+1][1] = r4[3];
            }
            {
                u32 addr = Kb + (u32)((((k0 + l + ((lane >> 3) & 1) * 8 + r) * 56) + 48) * 2);
                ldmx2t(bb[6], addr);
            }
            #pragma unroll
            for (int i = 0; i < 3; i++)
                #pragma unroll
                for (int j = 0; j < 7; j++) mma16(acc[i][j], a[i], bb[j]);
        }
        __syncthreads();
    }

    float* pb = part + (((long)ksb * NS_ + ns) * 5 + l) * (VQ_ * VK_);
    #pragma unroll
    for (int i = 0; i < 3; i++) {
        #pragma unroll
        for (int j = 0; j < 7; j++) {
            int u = uh * 48 + i * 16 + g;
            int v = j * 8 + 2 * tg;
            if (v < VK_) {
                if (u < VQ_) {
                    pb[u * VK_ + v]     = acc[i][j][0];
                    pb[u * VK_ + v + 1] = acc[i][j][1];
                }
                if (u + 8 < VQ_) {
                    pb[(u + 8) * VK_ + v]     = acc[i][j][2];
                    pb[(u + 8) * VK_ + v + 1] = acc[i][j][3];
                }
            }
        }
    }
}

// ---------------- combine lags + softmax -------------------------------------
__global__ __launch_bounds__(64)
void softmax_kernel(const float* __restrict__ part, float* __restrict__ att)
{
    const int row = blockIdx.x;
    const int ns = row / VQ_;
    const int u  = row - ns * VQ_;
    const int tid = threadIdx.x;
    const float inv_scale = rsqrtf((float)KTOT);

    __shared__ float red[64];
    float val = -1e30f;
    if (tid < VK_) {
        float mx = -1e30f, sm = 0.f;
        #pragma unroll
        for (int l = 0; l <= L_; l++) {
            float s = 0.f;
            #pragma unroll
            for (int ks = 0; ks < KSPLIT; ks++)
                s += part[((((long)ks * NS_ + ns) * 5 + l) * VQ_ + u) * VK_ + tid];
            mx = fmaxf(mx, s);
            sm += s;
        }
        val = 0.5f * (mx + sm * 0.2f) * inv_scale;
    }
    red[tid] = val; __syncthreads();
    for (int s = 32; s > 0; s >>= 1) {
        if (tid < s) red[tid] = fmaxf(red[tid], red[tid + s]);
        __syncthreads();
    }
    float rmax = red[0]; __syncthreads();
    float e = (tid < VK_) ? expf(val - rmax) : 0.f;
    red[tid] = e; __syncthreads();
    for (int s = 32; s > 0; s >>= 1) {
        if (tid < s) red[tid] += red[tid + s];
        __syncthreads();
    }
    float rsum = red[0];
    if (tid < VK_) att[(long)row * VK_ + tid] = e / rsum;
}

// ---------------- y = att @ V (tf32 mma, fp16 I/O, 4 s per block) ------------
#define YG_SMEM ((56*136 + 56*104) * 4)
__global__ __launch_bounds__(256)
void ygemm_mma(const __half* __restrict__ Vp, const float* __restrict__ att,
               __half* __restrict__ y)
{
    extern __shared__ u32 dynsh[];
    u32* Vs = dynsh;
    u32* Bs = dynsh + 56 * 136;

    const int ct0 = blockIdx.x * 128;
    const int n   = blockIdx.y;
    const __half* A = Vp + (long)n * (C_ * T_ * VK_) + (long)ct0 * VK_;

    const int tid = threadIdx.x, w = tid >> 5, lane = tid & 31;
    const int g = lane >> 2, tg = lane & 3;
    const int mw = (w & 3) * 32, nw = (w >> 2) * 48;

    for (int idx = tid; idx < 128 * 56; idx += 256) {
        int ct = idx / 56, k = idx - (idx / 56) * 56;
        Vs[k * 136 + ct] = (k < VK_) ? __float_as_uint(__half2float(A[ct * VK_ + k])) : 0u;
    }

    for (int s = 0; s < 4; s++) {
        const float* B = att + (long)(n * 4 + s) * (VQ_ * VK_);
        __half* Yb = y + (long)(n * 4 + s) * Y_PER_NS;
        for (int idx = tid; idx < 96 * 56; idx += 256) {
            int vq = idx / 56, k = idx - (idx / 56) * 56;
            Bs[k * 104 + vq] = (k < VK_ && vq < VQ_) ? tf32u(B[vq * VK_ + k]) : 0u;
        }
        __syncthreads();

        float acc[2][6][4];
        #pragma unroll
        for (int i = 0; i < 2; i++)
            #pragma unroll
            for (int j = 0; j < 6; j++)
                #pragma unroll
                for (int e = 0; e < 4; e++) acc[i][j][e] = 0.f;

        #pragma unroll
        for (int kq = 0; kq < 7; kq++) {
            const int k0 = kq * 8;
            u32 a[2][4];
            #pragma unroll
            for (int mi = 0; mi < 2; mi++) {
                int m = mw + mi * 16;
                a[mi][0] = Vs[(k0 + tg) * 136 + m + g];
                a[mi][1] = Vs[(k0 + tg) * 136 + m + g + 8];
                a[mi][2] = Vs[(k0 + tg + 4) * 136 + m + g];
                a[mi][3] = Vs[(k0 + tg + 4) * 136 + m + g + 8];
            }
            #pragma unroll
            for (int ji = 0; ji < 6; ji++) {
                u32 b[2];
                b[0] = Bs[(k0 + tg) * 104 + nw + ji * 8 + g];
                b[1] = Bs[(k0 + tg + 4) * 104 + nw + ji * 8 + g];
                mma8t(acc[0][ji], a[0], b);
                mma8t(acc[1][ji], a[1], b);
            }
        }
        #pragma unroll
        for (int mi = 0; mi < 2; mi++) {
            int ct = ct0 + mw + mi * 16 + g;
            #pragma unroll
            for (int ji = 0; ji < 6; ji++) {
                int vq = nw + ji * 8 + 2 * tg;
                if (vq < VQ_) {
                    *(__half2*)&Yb[(long)ct * VQ_ + vq] =
                        __floats2half2_rn(acc[mi][ji][0], acc[mi][ji][1]);
                    *(__half2*)&Yb[(long)(ct + 8) * VQ_ + vq] =
                        __floats2half2_rn(acc[mi][ji][2], acc[mi][ji][3]);
                }
            }
        }
        __syncthreads();
    }
}

// ---------------- BN finalize ------------------------------------------------
__global__ __launch_bounds__(256)
void bn_final(const float* __restrict__ partials,
              const float* __restrict__ gz, const float* __restrict__ bz,
              const float* __restrict__ gd, const float* __restrict__ bd,
              float* __restrict__ coef)
{
    const int which = blockIdx.x;
    const int tid = threadIdx.x;
    const int c = tid & 63, q = tid >> 6;
    const float2* p = (const float2*)partials + (long)which * NBLK_BN * 64;

    float a0 = 0.f, a1 = 0.f, b0 = 0.f, b1 = 0.f;
    for (int bb = 0; bb < 180; bb += 2) {
        float2 v0 = p[(long)(q * 180 + bb) * 64 + c];
        float2 v1 = p[(long)(q * 180 + bb + 1) * 64 + c];
        a0 += v0.x; b0 += v0.y;
        a1 += v1.x; b1 += v1.y;
    }
    __shared__ float r1[256], r2[256];
    r1[tid] = a0 + a1; r2[tid] = b0 + b1;
    __syncthreads();
    if (q == 0) {
        float s1 = r1[c] + r1[64 + c] + r1[128 + c] + r1[192 + c];
        float s2 = r2[c] + r2[64 + c] + r2[128 + c] + r2[192 + c];
        float inv = 1.0f / (float)BN_COUNT;
        float mean = s1 * inv;
        float var  = s2 * inv - mean * mean;
        float rstd = rsqrtf(var + 1e-5f);
        float gm = which ? gd[c] : gz[c];
        float bt = which ? bd[c] : bz[c];
        float a = gm * rstd;
        coef[(which * 64 + c) * 2 + 0] = a;
        coef[(which * 64 + c) * 2 + 1] = bt - mean * a;
    }
}

// ---------------- final epilogue ---------------------------------------------
__global__ __launch_bounds__(256)
void final_kernel(const float* __restrict__ z, const float* __restrict__ d,
                  const float* __restrict__ coef, float* __restrict__ out)
{
    long i4 = ((long)blockIdx.x * 256 + threadIdx.x) * 4;
    if (i4 >= OUT_TOTAL) return;
    int c = (int)((i4 / SPO) & (C_ - 1));
    float az = coef[c * 2], bz_ = coef[c * 2 + 1];
    float ad = coef[(C_ + c) * 2], bd_ = coef[(C_ + c) * 2 + 1];
    float4 zv = *(const float4*)&z[i4];
    float4 dv = *(const float4*)&d[i4];
    float4 o; float v;
    v = fmaf(az, zv.x, bz_) + fmaf(ad, dv.x, bd_); o.x = v > 0.f ? v : 0.1f * v;
    v = fmaf(az, zv.y, bz_) + fmaf(ad, dv.y, bd_); o.y = v > 0.f ? v : 0.1f * v;
    v = fmaf(az, zv.z, bz_) + fmaf(ad, dv.z, bd_); o.z = v > 0.f ? v : 0.1f * v;
    v = fmaf(az, zv.w, bz_) + fmaf(ad, dv.w, bd_); o.w = v > 0.f ? v : 0.1f * v;
    *(float4*)&out[i4] = o;
}

// ---------------- launch -----------------------------------------------------
extern "C" void kernel_launch(void* const* d_in, const int* in_sizes, int n_in,
                              void* d_out, int out_size)
{
    const float* x_q   = (const float*)d_in[0];
    const float* x_k   = (const float*)d_in[1];
    const float* x_v   = (const float*)d_in[2];
    const float* Wq    = (const float*)d_in[3];
    const float* bq    = (const float*)d_in[4];
    const float* Wk    = (const float*)d_in[5];
    const float* bk    = (const float*)d_in[6];
    const float* Wv    = (const float*)d_in[7];
    const float* bv    = (const float*)d_in[8];
    const float* Wout  = (const float*)d_in[9];
    const float* bout  = (const float*)d_in[10];
    const float* gout  = (const float*)d_in[11];
    const float* bnout = (const float*)d_in[12];
    const float* Wdown = (const float*)d_in[13];
    const float* bdown = (const float*)d_in[14];
    const float* gdown = (const float*)d_in[15];
    const float* bndwn = (const float*)d_in[16];

    __half *xqh, *xkh, *xvh, *Wqh, *Wkh, *Wvh, *Woh, *Wdh, *Qph, *Kph, *Vph, *yh;
    float *part, *att, *z, *dd, *bnp2, *coef;
    cudaGetSymbolAddress((void**)&xqh, g_xqh);
    cudaGetSymbolAddress((void**)&xkh, g_xkh);
    cudaGetSymbolAddress((void**)&xvh, g_xvh);
    cudaGetSymbolAddress((void**)&Wqh, g_Wqh);
    cudaGetSymbolAddress((void**)&Wkh, g_Wkh);
    cudaGetSymbolAddress((void**)&Wvh, g_Wvh);
    cudaGetSymbolAddress((void**)&Woh, g_Woh);
    cudaGetSymbolAddress((void**)&Wdh, g_Wdh);
    cudaGetSymbolAddress((void**)&Qph, g_Qph);
    cudaGetSymbolAddress((void**)&Kph, g_Kph);
    cudaGetSymbolAddress((void**)&Vph, g_Vph);
    cudaGetSymbolAddress((void**)&yh,  g_yh);
    cudaGetSymbolAddress((void**)&part, g_part);
    cudaGetSymbolAddress((void**)&att,  g_att);
    cudaGetSymbolAddress((void**)&z,    g_z);
    cudaGetSymbolAddress((void**)&dd,   g_d);
    cudaGetSymbolAddress((void**)&bnp2, g_bnp2);
    cudaGetSymbolAddress((void**)&coef, g_bncoef);

    cudaFuncSetAttribute(conv_h,  cudaFuncAttributeMaxDynamicSharedMemorySize, CONV_SMEM);
    cudaFuncSetAttribute(score_h, cudaFuncAttributeMaxDynamicSharedMemorySize, SC_SMEM);
    cudaFuncSetAttribute(ygemm_mma, cudaFuncAttributeMaxDynamicSharedMemorySize, YG_SMEM);

    // fp16 prep (inputs + weights)
    f2h<<<(11796480/2 + 255)/256, 256>>>(x_q, xqh, 11796480/2);
    f2h<<<(6553600/2 + 255)/256, 256>>>(x_k, xkh, 6553600/2);
    f2h<<<(6553600/2 + 255)/256, 256>>>(x_v, xvh, 6553600/2);
    f2h<<<32, 256>>>(Wq, Wqh, 8192);
    f2h<<<32, 256>>>(Wk, Wkh, 8192);
    f2h<<<8, 256>>>(Wv, Wvh, 2048);
    f2h<<<32, 256>>>(Wout, Woh, 8192);
    f2h<<<8, 256>>>(Wdown, Wdh, 2048);

    // projections (fp16 HMMA)
    conv_h<<<dim3(89, 4, N_), 256, CONV_SMEM>>>(Wqh, bq, xqh, nullptr, Qph, 90, QPAD,
        64, SPQ, SPO, 1474560L, (long)SC_*Tq_*QPAD, nullptr);
    conv_h<<<dim3(50, 4, N_), 256, CONV_SMEM>>>(Wkh, bk, xkh, nullptr, Kph, 50, KPAD,
        64, SPK, SPK, 819200L, (long)SC_*T_*KPAD, nullptr);
    conv_h<<<dim3(50, 1, N_), 256, CONV_SMEM>>>(Wvh, bv, xvh, nullptr, Vph, 50, 50,
        64, SPK, SPK, 819200L, 819200L, nullptr);
    conv_h<<<dim3(90, 1, N_), 256, CONV_SMEM>>>(Wdh, bdown, xqh, dd, nullptr, 0, 0,
        64, SPO, SPO, 1474560L, 1474560L, bnp2 + 2L * NBLK_BN * 64);

    // multi-lag scores (fp16 HMMA) + softmax
    score_h<<<dim3(NS_, KSPLIT), 320, SC_SMEM>>>(Qph, Kph, part);
    softmax_kernel<<<NS_ * VQ_, 64>>>(part, att);

    // y = att @ V, out projection
    ygemm_mma<<<dim3(128, N_), 256, YG_SMEM>>>(Vph, att, yh);
    conv_h<<<dim3(90, 1, N_), 256, CONV_SMEM>>>(Woh, bout, yh, z, nullptr, 0, 0,
        256, SPO, SPO, 5898240L, 1474560L, bnp2);

    // BN finalize + fused epilogue
    bn_final<<<2, 256>>>(bnp2, gout, bnout, gdown, bndwn, coef);
    final_kernel<<<(OUT_TOTAL / 4 + 255) / 256, 256>>>(z, dd, coef, (float*)d_out);
}

// round 17
// speedup vs baseline: 1.3516x; 1.3516x over previous
#include <cuda_runtime.h>
#include <cuda_fp16.h>
#include <math.h>

#define N_   8
#define C_   64
#define T_   256
#define VQ_  90
#define VK_  50
#define L_   4
#define Tq_  252
#define SC_  256
#define NS_  32
#define KSPLIT 8
#define CPB   8
#define KTOT 16128
#define SPQ  22680
#define SPK  12800
#define SPO  23040
#define OUT_TOTAL 11796480
#define BN_COUNT  184320
#define NBLK_BN 720
#define VP_PER_N 819200
#define Y_PER_NS 1474560
#define QPAD 96
#define KPAD 56

typedef unsigned long long u64;
typedef unsigned int u32;

// ---- mma helpers (base PTX, validated R9-R16) -------------------------------
__device__ __forceinline__ u32 tf32u(float x) {
    u32 r; asm("cvt.rna.tf32.f32 %0, %1;" : "=r"(r) : "f"(x)); return r;
}
__device__ __forceinline__ u32 tf32s(u32 raw) {
    u32 r; asm("cvt.rna.tf32.f32 %0, %1;" : "=r"(r) : "f"(__uint_as_float(raw)));
    return r;
}
__device__ __forceinline__ void mma8t(float* c, const u32* a, const u32* b) {
    asm volatile("mma.sync.aligned.m16n8k8.row.col.f32.tf32.tf32.f32 "
        "{%0,%1,%2,%3},{%4,%5,%6,%7},{%8,%9},{%0,%1,%2,%3};"
        : "+f"(c[0]), "+f"(c[1]), "+f"(c[2]), "+f"(c[3])
        : "r"(a[0]), "r"(a[1]), "r"(a[2]), "r"(a[3]), "r"(b[0]), "r"(b[1]));
}
__device__ __forceinline__ void mma16(float* c, const u32* a, const u32* b) {
    asm volatile("mma.sync.aligned.m16n8k16.row.col.f32.f16.f16.f32 "
        "{%0,%1,%2,%3},{%4,%5,%6,%7},{%8,%9},{%0,%1,%2,%3};"
        : "+f"(c[0]), "+f"(c[1]), "+f"(c[2]), "+f"(c[3])
        : "r"(a[0]), "r"(a[1]), "r"(a[2]), "r"(a[3]), "r"(b[0]), "r"(b[1]));
}
__device__ __forceinline__ void ldmx4t(u32* r, u32 addr) {
    asm volatile("ldmatrix.sync.aligned.m8n8.x4.trans.shared.b16 {%0,%1,%2,%3},[%4];"
        : "=r"(r[0]), "=r"(r[1]), "=r"(r[2]), "=r"(r[3]) : "r"(addr));
}
__device__ __forceinline__ void ldmx2t(u32* r, u32 addr) {
    asm volatile("ldmatrix.sync.aligned.m8n8.x2.trans.shared.b16 {%0,%1},[%2];"
        : "=r"(r[0]), "=r"(r[1]) : "r"(addr));
}
__device__ __forceinline__ u32 smem_u32(const void* p) {
    u32 a; asm("{ .reg .u64 t; cvta.to.shared.u64 t, %1; cvt.u32.u64 %0, t; }" : "=r"(a) : "l"(p));
    return a;
}
__device__ __forceinline__ void cpa16(u32 dst, const void* src, u32 bytes) {
    asm volatile("cp.async.ca.shared.global [%0], [%1], 16, %2;" :: "r"(dst), "l"(src), "r"(bytes));
}
__device__ __forceinline__ void cpa_commit() { asm volatile("cp.async.commit_group;"); }
__device__ __forceinline__ void cpa_wait2() { asm volatile("cp.async.wait_group 2;" ::: "memory"); }
__device__ __forceinline__ void cpa_wait1() { asm volatile("cp.async.wait_group 1;" ::: "memory"); }
__device__ __forceinline__ void cpa_wait0() { asm volatile("cp.async.wait_group 0;" ::: "memory"); }

// ---------------- scratch ----------------------------------------------------
__device__ __half g_Qph[(long)NS_*C_*Tq_*QPAD];   // [ns][c][t][u96], pads stay 0
__device__ __half g_Kph[(long)NS_*C_*T_*KPAD];    // [ns][c][t][v56], pads stay 0
__device__ float g_Vp[(long)N_*C_*T_*VK_];
__device__ float g_part[(long)KSPLIT*NS_*(L_+1)*VQ_*VK_];
__device__ float g_att[(long)NS_*VQ_*VK_];
__device__ float g_y[(long)N_*SC_*T_*VQ_];
__device__ float g_z[(long)OUT_TOTAL];
__device__ float g_d[(long)OUT_TOTAL];
__device__ float g_bnp2[2L*NBLK_BN*64*2];
__device__ float g_bncoef[2*C_*2];

// ---------------- conv1x1 via tf32 mma, cp.async 4-stage ---------------------
// Y[n][m][sp] = sum_k W[m][k] X[n][k][sp] + b[m]
// Yh != null: emit fp16 with (ulen -> upad) row remap. Else f32 (+BN partials).
#define CONV_BUF_W (64*20)
#define CONV_BUF_X (16*264)
#define CONV_BUF   (CONV_BUF_W + CONV_BUF_X)
#define CONV_SMEM  (4 * CONV_BUF * 4)
__global__ __launch_bounds__(256, 2)
void conv_mma(const float* __restrict__ W, const float* __restrict__ bias,
              const float* __restrict__ X, float* Yf, __half* Yh,
              int ulen, int upad, int K, int Nsp, int ldx,
              long xbatch, long ybatch, float* bnsum)
{
    extern __shared__ u32 cdyn[];
    const int n  = blockIdx.z;
    const int m0 = blockIdx.y * 64;
    const int n0 = blockIdx.x * 256;
    const float* Xn = X + (long)n * xbatch;

    const int tid = threadIdx.x, w = tid >> 5, lane = tid & 31;
    const int g = lane >> 2, tg = lane & 3;
    const int mw = (w & 1) * 32, nw = (w >> 1) * 64;
    const int KT = K >> 4;
    const u32 smem0 = smem_u32(cdyn);

    const int wm = tid >> 2, wck = (tid & 3) * 4;

    auto issue = [&](int kt) {
        const u32 base = smem0 + (u32)(kt & 3) * (CONV_BUF * 4);
        const int k0 = kt * 16;
        cpa16(base + (wm * 20 + wck) * 4, &W[(long)(m0 + wm) * K + k0 + wck], 16);
        #pragma unroll
        for (int p = 0; p < 4; p++) {
            int i = p * 256 + tid;
            int kk = i >> 6, j4 = (i & 63) * 4;
            int col = n0 + j4;
            int bytes = (Nsp - col) * 4;
            bytes = bytes < 0 ? 0 : (bytes > 16 ? 16 : bytes);
            const float* src = &Xn[(long)(k0 + kk) * ldx + (col < Nsp ? col : 0)];
            cpa16(base + (CONV_BUF_W + kk * 264 + j4) * 4, src, (u32)bytes);
        }
        cpa_commit();
    };

    float acc[2][8][4];
    #pragma unroll
    for (int i = 0; i < 2; i++)
        #pragma unroll
        for (int j = 0; j < 8; j++)
            #pragma unroll
            for (int e = 0; e < 4; e++) acc[i][j][e] = 0.f;

    issue(0);
    if (KT > 1) issue(1);
    if (KT > 2) issue(2);

    for (int kt = 0; kt < KT; kt++) {
        int rem = KT - kt - 1; rem = rem > 2 ? 2 : rem;
        if (rem == 2) cpa_wait2(); else if (rem == 1) cpa_wait1(); else cpa_wait0();
        __syncthreads();
        if (kt + 3 < KT) issue(kt + 3);
        const u32* Wb = cdyn + (kt & 3) * CONV_BUF;
        const u32* Xb = Wb + CONV_BUF_W;
        #pragma unroll
        for (int k8 = 0; k8 < 16; k8 += 8) {
            u32 a[2][4];
            #pragma unroll
            for (int mi = 0; mi < 2; mi++) {
                int m = mw + mi * 16;
                a[mi][0] = tf32s(Wb[(m + g) * 20 + k8 + tg]);
                a[mi][1] = tf32s(Wb[(m + g + 8) * 20 + k8 + tg]);
                a[mi][2] = tf32s(Wb[(m + g) * 20 + k8 + tg + 4]);
                a[mi][3] = tf32s(Wb[(m + g + 8) * 20 + k8 + tg + 4]);
            }
            #pragma unroll
            for (int ji = 0; ji < 8; ji++) {
                u32 b[2];
                b[0] = tf32s(Xb[(k8 + tg) * 264 + nw + ji * 8 + g]);
                b[1] = tf32s(Xb[(k8 + tg + 4) * 264 + nw + ji * 8 + g]);
                mma8t(acc[0][ji], a[0], b);
                mma8t(acc[1][ji], a[1], b);
            }
        }
        __syncthreads();
    }

    if (Yh) {   // fp16 output, remap sp=(t*ulen+u) -> [m][t][upad]
        __half* Yn = Yh + (long)n * ybatch;
        const int TR = Nsp / ulen;
        #pragma unroll
        for (int mi = 0; mi < 2; mi++) {
            int mrow = m0 + mw + mi * 16 + g;
            float bv0 = bias[mrow], bv1 = bias[mrow + 8];
            #pragma unroll
            for (int ji = 0; ji < 8; ji++) {
                int sp = n0 + nw + ji * 8 + 2 * tg;
                if (sp < Nsp) {
                    int t = sp / ulen, u = sp - t * ulen;
                    __half2 h0 = __floats2half2_rn(acc[mi][ji][0] + bv0, acc[mi][ji][1] + bv0);
                    __half2 h1 = __floats2half2_rn(acc[mi][ji][2] + bv1, acc[mi][ji][3] + bv1);
                    long o0 = ((long)mrow * TR + t) * upad + u;
                    long o1 = ((long)(mrow + 8) * TR + t) * upad + u;
                    if (u + 1 < ulen) {        // always true here (u even < ulen-1)
                        *(__half2*)&Yn[o0] = h0;
                        *(__half2*)&Yn[o1] = h1;
                    } else {
                        Yn[o0] = __low2half(h0);
                        Yn[((long)mrow * TR + t + 1) * upad] = __high2half(h0);
                        Yn[o1] = __low2half(h1);
                        Yn[((long)(mrow + 8) * TR + t + 1) * upad] = __high2half(h1);
                    }
                }
            }
        }
    } else {
        float* Yn = Yf + (long)n * ybatch;
        float s1l[4] = {0.f,0.f,0.f,0.f}, s2l[4] = {0.f,0.f,0.f,0.f};
        #pragma unroll
        for (int mi = 0; mi < 2; mi++) {
            int mrow = m0 + mw + mi * 16 + g;
            float bv0 = bias[mrow], bv1 = bias[mrow + 8];
            #pragma unroll
            for (int ji = 0; ji < 8; ji++) {
                int col = n0 + nw + ji * 8 + 2 * tg;
                if (col < Nsp) {
                    float2 o0; o0.x = acc[mi][ji][0] + bv0; o0.y = acc[mi][ji][1] + bv0;
                    float2 o1; o1.x = acc[mi][ji][2] + bv1; o1.y = acc[mi][ji][3] + bv1;
                    *(float2*)&Yn[(long)mrow * Nsp + col] = o0;
                    *(float2*)&Yn[(long)(mrow + 8) * Nsp + col] = o1;
                    if (bnsum) {
                        s1l[mi*2+0] += o0.x + o0.y;  s2l[mi*2+0] += o0.x*o0.x + o0.y*o0.y;
                        s1l[mi*2+1] += o1.x + o1.y;  s2l[mi*2+1] += o1.x*o1.x + o1.y*o1.y;
                    }
                }
            }
        }
        if (bnsum) {
            #pragma unroll
            for (int rr = 0; rr < 4; rr++) {
                s1l[rr] += __shfl_xor_sync(0xffffffffu, s1l[rr], 1);
                s1l[rr] += __shfl_xor_sync(0xffffffffu, s1l[rr], 2);
                s2l[rr] += __shfl_xor_sync(0xffffffffu, s2l[rr], 1);
                s2l[rr] += __shfl_xor_sync(0xffffffffu, s2l[rr], 2);
            }
            float* bs = (float*)cdyn;
            if (tg == 0) {
                #pragma unroll
                for (int rr = 0; rr < 4; rr++) {
                    int row = mw + (rr >> 1) * 16 + g + (rr & 1) * 8;
                    bs[(row * 4 + (w >> 1)) * 2 + 0] = s1l[rr];
                    bs[(row * 4 + (w >> 1)) * 2 + 1] = s2l[rr];
                }
            }
            __syncthreads();
            if (tid < 64) {
                float a1 = 0.f, a2 = 0.f;
                #pragma unroll
                for (int j = 0; j < 4; j++) {
                    a1 += bs[(tid * 4 + j) * 2 + 0];
                    a2 += bs[(tid * 4 + j) * 2 + 1];
                }
                int blk = blockIdx.x * gridDim.z + blockIdx.z;
                ((float2*)bnsum)[(long)blk * 64 + tid] = make_float2(a1, a2);
            }
        }
    }
}

// ---------------- score: fp16 m16n8k16 + ldmatrix, cp.async 4-stage ----------
// (validated in R16) part_l[u][v] = sum_{c,t} Qp[ns][c][t][u] * Kp[ns][c][t+l][v]
#define SQ_B (32*104*2)
#define SK_B (36*56*2)
#define SC_BUF (SQ_B + SK_B)
#define SC_SMEM (4 * SC_BUF)
__global__ __launch_bounds__(320)
void score_h(const __half* __restrict__ Qh, const __half* __restrict__ Kh,
             float* __restrict__ part)
{
    extern __shared__ char smc[];
    const int ns = blockIdx.x, ksb = blockIdx.y;
    const int tid = threadIdx.x, w = tid >> 5, lane = tid & 31;
    const int g = lane >> 2, tg = lane & 3;
    const int grp = lane >> 3, r = lane & 7;
    const int l = w >> 1, uh = w & 1;
    const __half* Qns = Qh + (long)ns * C_ * Tq_ * QPAD;
    const __half* Kns = Kh + (long)ns * C_ * T_ * KPAD;
    const u32 sm0 = smem_u32(smc);

    int jrow[2], jch[2], jq[2];
    u32 jdst[2];
    #pragma unroll
    for (int p = 0; p < 2; p++) {
        int id = tid + p * 320;
        if (id < 384) {
            jq[p] = 1; jrow[p] = id / 12; jch[p] = id % 12;
            jdst[p] = (u32)((jrow[p] * 104 + jch[p] * 8) * 2);
        } else if (id < 636) {
            int id2 = id - 384;
            jq[p] = 0; jrow[p] = id2 / 7; jch[p] = id2 % 7;
            jdst[p] = (u32)(SQ_B + (jrow[p] * 56 + jch[p] * 8) * 2);
        } else jq[p] = -1;
    }

    auto issue = [&](int it) {
        const int c = ksb * CPB + (it >> 3), tt = it & 7;
        const int t0 = tt * 32;
        const u32 base = sm0 + (u32)(it & 3) * SC_BUF;
        const __half* Qc = Qns + (long)c * Tq_ * QPAD;
        const __half* Kc = Kns + (long)c * T_ * KPAD;
        #pragma unroll
        for (int p = 0; p < 2; p++) {
            if (jq[p] == 1) {
                int t = t0 + jrow[p];
                u32 sz = (t < Tq_) ? (jch[p] == 11 ? 4u : 16u) : 0u;
                cpa16(base + jdst[p], sz ? (Qc + (long)t * QPAD + jch[p] * 8) : Qc, sz);
            } else if (jq[p] == 0) {
                int t = t0 + jrow[p];
                u32 sz = (t < T_) ? (jch[p] == 6 ? 4u : 16u) : 0u;
                cpa16(base + jdst[p], sz ? (Kc + (long)t * KPAD + jch[p] * 8) : Kc, sz);
            }
        }
        cpa_commit();
    };

    float acc[3][7][4];
    #pragma unroll
    for (int i = 0; i < 3; i++)
        #pragma unroll
        for (int j = 0; j < 7; j++)
            #pragma unroll
            for (int e = 0; e < 4; e++) acc[i][j][e] = 0.f;

    const int NT = CPB * 8;
    issue(0); issue(1); issue(2);

    for (int it = 0; it < NT; it++) {
        int rem = NT - it - 1; rem = rem > 2 ? 2 : rem;
        if (rem == 2) cpa_wait2(); else if (rem == 1) cpa_wait1(); else cpa_wait0();
        __syncthreads();
        if (it + 3 < NT) issue(it + 3);
        const u32 Qb = sm0 + (u32)(it & 3) * SC_BUF;
        const u32 Kb = Qb + SQ_B;
        #pragma unroll
        for (int k16 = 0; k16 < 2; k16++) {
            const int k0 = k16 * 16;
            u32 a[3][4], bb[7][2];
            #pragma unroll
            for (int i = 0; i < 3; i++) {
                u32 addr = Qb + (u32)((((k0 + (grp >> 1) * 8 + r) * 104)
                           + uh * 48 + i * 16 + (grp & 1) * 8) * 2);
                ldmx4t(a[i], addr);
            }
            #pragma unroll
            for (int j2 = 0; j2 < 3; j2++) {
                u32 r4[4];
                u32 addr = Kb + (u32)((((k0 + l + (grp & 1) * 8 + r) * 56)
                           + j2 * 16 + (grp >> 1) * 8) * 2);
                ldmx4t(r4, addr);
                bb[2*j2][0] = r4[0]; bb[2*j2][1] = r4[1];
                bb[2*j2+1][0] = r4[2]; bb[2*j2+1][1] = r4[3];
            }
            {
                u32 addr = Kb + (u32)((((k0 + l + ((lane >> 3) & 1) * 8 + r) * 56) + 48) * 2);
                ldmx2t(bb[6], addr);
            }
            #pragma unroll
            for (int i = 0; i < 3; i++)
                #pragma unroll
                for (int j = 0; j < 7; j++) mma16(acc[i][j], a[i], bb[j]);
        }
        __syncthreads();
    }

    float* pb = part + (((long)ksb * NS_ + ns) * 5 + l) * (VQ_ * VK_);
    #pragma unroll
    for (int i = 0; i < 3; i++) {
        #pragma unroll
        for (int j = 0; j < 7; j++) {
            int u = uh * 48 + i * 16 + g;
            int v = j * 8 + 2 * tg;
            if (v < VK_) {
                if (u < VQ_) {
                    pb[u * VK_ + v]     = acc[i][j][0];
                    pb[u * VK_ + v + 1] = acc[i][j][1];
                }
                if (u + 8 < VQ_) {
                    pb[(u + 8) * VK_ + v]     = acc[i][j][2];
                    pb[(u + 8) * VK_ + v + 1] = acc[i][j][3];
                }
            }
        }
    }
}

// ---------------- combine lags + softmax -------------------------------------
__global__ __launch_bounds__(64)
void softmax_kernel(const float* __restrict__ part, float* __restrict__ att)
{
    const int row = blockIdx.x;
    const int ns = row / VQ_;
    const int u  = row - ns * VQ_;
    const int tid = threadIdx.x;
    const float inv_scale = rsqrtf((float)KTOT);

    __shared__ float red[64];
    float val = -1e30f;
    if (tid < VK_) {
        float mx = -1e30f, sm = 0.f;
        #pragma unroll
        for (int l = 0; l <= L_; l++) {
            float s = 0.f;
            #pragma unroll
            for (int ks = 0; ks < KSPLIT; ks++)
                s += part[((((long)ks * NS_ + ns) * 5 + l) * VQ_ + u) * VK_ + tid];
            mx = fmaxf(mx, s);
            sm += s;
        }
        val = 0.5f * (mx + sm * 0.2f) * inv_scale;
    }
    red[tid] = val; __syncthreads();
    for (int s = 32; s > 0; s >>= 1) {
        if (tid < s) red[tid] = fmaxf(red[tid], red[tid + s]);
        __syncthreads();
    }
    float rmax = red[0]; __syncthreads();
    float e = (tid < VK_) ? expf(val - rmax) : 0.f;
    red[tid] = e; __syncthreads();
    for (int s = 32; s > 0; s >>= 1) {
        if (tid < s) red[tid] += red[tid + s];
        __syncthreads();
    }
    float rsum = red[0];
    if (tid < VK_) att[(long)row * VK_ + tid] = e / rsum;
}

// ---------------- y = att @ V, 4 s per block (unchanged from R15) ------------
#define YG_SMEM ((56*136 + 56*104) * 4)
__global__ __launch_bounds__(256)
void ygemm_mma(const float* __restrict__ Vp, const float* __restrict__ att,
               float* __restrict__ y)
{
    extern __shared__ u32 dynsh[];
    u32* Vs = dynsh;
    u32* Bs = dynsh + 56 * 136;

    const int ct0 = blockIdx.x * 128;
    const int n   = blockIdx.y;
    const float* A = Vp + (long)n * VP_PER_N + (long)ct0 * VK_;

    const int tid = threadIdx.x, w = tid >> 5, lane = tid & 31;
    const int g = lane >> 2, tg = lane & 3;
    const int mw = (w & 3) * 32, nw = (w >> 2) * 48;

    for (int idx = tid; idx < 128 * 56; idx += 256) {
        int ct = idx / 56, k = idx - (idx / 56) * 56;
        Vs[k * 136 + ct] = (k < VK_) ? tf32u(A[ct * VK_ + k]) : 0u;
    }

    for (int s = 0; s < 4; s++) {
        const float* B = att + (long)(n * 4 + s) * (VQ_ * VK_);
        float* Yb = y + (long)(n * 4 + s) * Y_PER_NS;
        for (int idx = tid; idx < 96 * 56; idx += 256) {
            int vq = idx / 56, k = idx - (idx / 56) * 56;
            Bs[k * 104 + vq] = (k < VK_ && vq < VQ_) ? tf32u(B[vq * VK_ + k]) : 0u;
        }
        __syncthreads();

        float acc[2][6][4];
        #pragma unroll
        for (int i = 0; i < 2; i++)
            #pragma unroll
            for (int j = 0; j < 6; j++)
                #pragma unroll
                for (int e = 0; e < 4; e++) acc[i][j][e] = 0.f;

        #pragma unroll
        for (int kq = 0; kq < 7; kq++) {
            const int k0 = kq * 8;
            u32 a[2][4];
            #pragma unroll
            for (int mi = 0; mi < 2; mi++) {
                int m = mw + mi * 16;
                a[mi][0] = Vs[(k0 + tg) * 136 + m + g];
                a[mi][1] = Vs[(k0 + tg) * 136 + m + g + 8];
                a[mi][2] = Vs[(k0 + tg + 4) * 136 + m + g];
                a[mi][3] = Vs[(k0 + tg + 4) * 136 + m + g + 8];
            }
            #pragma unroll
            for (int ji = 0; ji < 6; ji++) {
                u32 b[2];
                b[0] = Bs[(k0 + tg) * 104 + nw + ji * 8 + g];
                b[1] = Bs[(k0 + tg + 4) * 104 + nw + ji * 8 + g];
                mma8t(acc[0][ji], a[0], b);
                mma8t(acc[1][ji], a[1], b);
            }
        }
        #pragma unroll
        for (int mi = 0; mi < 2; mi++) {
            int ct = ct0 + mw + mi * 16 + g;
            #pragma unroll
            for (int ji = 0; ji < 6; ji++) {
                int vq = nw + ji * 8 + 2 * tg;
                if (vq < VQ_) {
                    float2 o0; o0.x = acc[mi][ji][0]; o0.y = acc[mi][ji][1];
                    float2 o1; o1.x = acc[mi][ji][2]; o1.y = acc[mi][ji][3];
                    *(float2*)&Yb[(long)ct * VQ_ + vq] = o0;
                    *(float2*)&Yb[(long)(ct + 8) * VQ_ + vq] = o1;
                }
            }
        }
        __syncthreads();
    }
}

// ---------------- BN finalize ------------------------------------------------
__global__ __launch_bounds__(256)
void bn_final(const float* __restrict__ partials,
              const float* __restrict__ gz, const float* __restrict__ bz,
              const float* __restrict__ gd, const float* __restrict__ bd,
              float* __restrict__ coef)
{
    const int which = blockIdx.x;
    const int tid = threadIdx.x;
    const int c = tid & 63, q = tid >> 6;
    const float2* p = (const float2*)partials + (long)which * NBLK_BN * 64;

    float a0 = 0.f, a1 = 0.f, b0 = 0.f, b1 = 0.f;
    for (int bb = 0; bb < 180; bb += 2) {
        float2 v0 = p[(long)(q * 180 + bb) * 64 + c];
        float2 v1 = p[(long)(q * 180 + bb + 1) * 64 + c];
        a0 += v0.x; b0 += v0.y;
        a1 += v1.x; b1 += v1.y;
    }
    __shared__ float r1[256], r2[256];
    r1[tid] = a0 + a1; r2[tid] = b0 + b1;
    __syncthreads();
    if (q == 0) {
        float s1 = r1[c] + r1[64 + c] + r1[128 + c] + r1[192 + c];
        float s2 = r2[c] + r2[64 + c] + r2[128 + c] + r2[192 + c];
        float inv = 1.0f / (float)BN_COUNT;
        float mean = s1 * inv;
        float var  = s2 * inv - mean * mean;
        float rstd = rsqrtf(var + 1e-5f);
        float gm = which ? gd[c] : gz[c];
        float bt = which ? bd[c] : bz[c];
        float a = gm * rstd;
        coef[(which * 64 + c) * 2 + 0] = a;
        coef[(which * 64 + c) * 2 + 1] = bt - mean * a;
    }
}

// ---------------- final epilogue ---------------------------------------------
__global__ __launch_bounds__(256)
void final_kernel(const float* __restrict__ z, const float* __restrict__ d,
                  const float* __restrict__ coef, float* __restrict__ out)
{
    long i4 = ((long)blockIdx.x * 256 + threadIdx.x) * 4;
    if (i4 >= OUT_TOTAL) return;
    int c = (int)((i4 / SPO) & (C_ - 1));
    float az = coef[c * 2], bz_ = coef[c * 2 + 1];
    float ad = coef[(C_ + c) * 2], bd_ = coef[(C_ + c) * 2 + 1];
    float4 zv = *(const float4*)&z[i4];
    float4 dv = *(const float4*)&d[i4];
    float4 o; float v;
    v = fmaf(az, zv.x, bz_) + fmaf(ad, dv.x, bd_); o.x = v > 0.f ? v : 0.1f * v;
    v = fmaf(az, zv.y, bz_) + fmaf(ad, dv.y, bd_); o.y = v > 0.f ? v : 0.1f * v;
    v = fmaf(az, zv.z, bz_) + fmaf(ad, dv.z, bd_); o.z = v > 0.f ? v : 0.1f * v;
    v = fmaf(az, zv.w, bz_) + fmaf(ad, dv.w, bd_); o.w = v > 0.f ? v : 0.1f * v;
    *(float4*)&out[i4] = o;
}

// ---------------- launch -----------------------------------------------------
extern "C" void kernel_launch(void* const* d_in, const int* in_sizes, int n_in,
                              void* d_out, int out_size)
{
    const float* x_q   = (const float*)d_in[0];
    const float* x_k   = (const float*)d_in[1];
    const float* x_v   = (const float*)d_in[2];
    const float* Wq    = (const float*)d_in[3];
    const float* bq    = (const float*)d_in[4];
    const float* Wk    = (const float*)d_in[5];
    const float* bk    = (const float*)d_in[6];
    const float* Wv    = (const float*)d_in[7];
    const float* bv    = (const float*)d_in[8];
    const float* Wout  = (const float*)d_in[9];
    const float* bout  = (const float*)d_in[10];
    const float* gout  = (const float*)d_in[11];
    const float* bnout = (const float*)d_in[12];
    const float* Wdown = (const float*)d_in[13];
    const float* bdown = (const float*)d_in[14];
    const float* gdown = (const float*)d_in[15];
    const float* bndwn = (const float*)d_in[16];

    __half *Qph, *Kph;
    float *Vp, *part, *att, *y, *z, *dd, *bnp2, *coef;
    cudaGetSymbolAddress((void**)&Qph, g_Qph);
    cudaGetSymbolAddress((void**)&Kph, g_Kph);
    cudaGetSymbolAddress((void**)&Vp,  g_Vp);
    cudaGetSymbolAddress((void**)&part, g_part);
    cudaGetSymbolAddress((void**)&att,  g_att);
    cudaGetSymbolAddress((void**)&y,    g_y);
    cudaGetSymbolAddress((void**)&z,    g_z);
    cudaGetSymbolAddress((void**)&dd,   g_d);
    cudaGetSymbolAddress((void**)&bnp2, g_bnp2);
    cudaGetSymbolAddress((void**)&coef, g_bncoef);

    cudaFuncSetAttribute(conv_mma, cudaFuncAttributeMaxDynamicSharedMemorySize, CONV_SMEM);
    cudaFuncSetAttribute(score_h,  cudaFuncAttributeMaxDynamicSharedMemorySize, SC_SMEM);
    cudaFuncSetAttribute(ygemm_mma, cudaFuncAttributeMaxDynamicSharedMemorySize, YG_SMEM);

    // projections: Q/K emit fp16 padded score operands; V/down stay f32
    conv_mma<<<dim3(89, 4, N_), 256, CONV_SMEM>>>(Wq, bq, x_q, nullptr, Qph, 90, QPAD,
        64, SPQ, SPO, 1474560L, (long)SC_*Tq_*QPAD, nullptr);
    conv_mma<<<dim3(50, 4, N_), 256, CONV_SMEM>>>(Wk, bk, x_k, nullptr, Kph, 50, KPAD,
        64, SPK, SPK, 819200L, (long)SC_*T_*KPAD, nullptr);
    conv_mma<<<dim3(50, 1, N_), 256, CONV_SMEM>>>(Wv, bv, x_v, Vp, nullptr, 0, 0,
        64, SPK, SPK, 819200L, 819200L, nullptr);
    conv_mma<<<dim3(90, 1, N_), 256, CONV_SMEM>>>(Wdown, bdown, x_q, dd, nullptr, 0, 0,
        64, SPO, SPO, 1474560L, 1474560L, bnp2 + 2L * NBLK_BN * 64);

    // fp16 multi-lag scores + softmax
    score_h<<<dim3(NS_, KSPLIT), 320, SC_SMEM>>>(Qph, Kph, part);
    softmax_kernel<<<NS_ * VQ_, 64>>>(part, att);

    // y = att @ V, out projection (emits BN partials)
    ygemm_mma<<<dim3(128, N_), 256, YG_SMEM>>>(Vp, att, y);
    conv_mma<<<dim3(90, 1, N_), 256, CONV_SMEM>>>(Wout, bout, y, z, nullptr, 0, 0,
        256, SPO, SPO, 5898240L, 1474560L, bnp2);

    // BN finalize + fused epilogue
    bn_final<<<2, 256>>>(bnp2, gout, bnout, gdown, bndwn, coef);
    final_kernel<<<(OUT_TOTAL / 4 + 255) / 256, 256>>>(z, dd, coef, (float*)d_out);
}